// round 13
// baseline (speedup 1.0000x reference)
#include <cuda_runtime.h>
#include <cuda_fp16.h>
#include <stdint.h>

// Problem constants (fixed by the dataset)
#define NMAX   50000
#define EMAX   800000
#define GMAX   64
#define HID    128
#define OUTF   64

// ---------------- device scratch (no allocations allowed) ----------------
// All zero at module load. Self-cleaning: every kernel that consumes
// call-scoped state zeroes it for the next call (g_cnt in k_scan_lb,
// g_tilestate in k_fill, g_poolsum/g_gcnt in k_pooldiv).
__device__ int                    g_cnt[NMAX];
__device__ unsigned int           g_tilestate[64];   // lookback scan state
__device__ int                    g_rowptr[NMAX + 1];
__device__ int                    g_pos[NMAX];
__device__ int                    g_csr_src[EMAX];
__device__ float                  g_dinv[NMAX];
__device__ __align__(16) float    g_X8[NMAX * 8];    // dinv[i]*x[i], padded to 8
__device__ __align__(16) __half   g_Th[NMAX * HID];  // dinv-scaled GEMM outputs (fp16)
__device__ __align__(16) float    g_H[NMAX * HID];   // activations (fp32)
__device__ float                  g_poolsum[GMAX * OUTF];
__device__ int                    g_gcnt[GMAX];

// ---------------- tf32 helpers ----------------
__device__ __forceinline__ uint32_t f2tf32(float f) {
    uint32_t r;
    asm("cvt.rna.tf32.f32 %0, %1;" : "=r"(r) : "f"(f));
    return r;
}
__device__ __forceinline__ void mma_tf32(float* c, const uint32_t* a,
                                         uint32_t b0, uint32_t b1) {
    asm("mma.sync.aligned.m16n8k8.row.col.f32.tf32.tf32.f32 "
        "{%0,%1,%2,%3}, {%4,%5,%6,%7}, {%8,%9}, {%0,%1,%2,%3};"
        : "+f"(c[0]), "+f"(c[1]), "+f"(c[2]), "+f"(c[3])
        : "r"(a[0]), "r"(a[1]), "r"(a[2]), "r"(a[3]), "r"(b0), "r"(b1));
}

// unpack uint4 (8 halves) and add into 8 fp32 accumulators
__device__ __forceinline__ void h8_add(float* acc, uint4 u) {
    const __half2* h = reinterpret_cast<const __half2*>(&u);
    float2 f0 = __half22float2(h[0]);
    float2 f1 = __half22float2(h[1]);
    float2 f2 = __half22float2(h[2]);
    float2 f3 = __half22float2(h[3]);
    acc[0] += f0.x; acc[1] += f0.y; acc[2] += f1.x; acc[3] += f1.y;
    acc[4] += f2.x; acc[5] += f2.y; acc[6] += f3.x; acc[7] += f3.y;
}

// ---------------- setup: degree + graph-size histograms ----------------
__global__ void k_hist(const int* __restrict__ ei, const int* __restrict__ batch,
                       int e, int n) {
    int i = blockIdx.x * blockDim.x + threadIdx.x;
    if (i < e) atomicAdd(&g_cnt[ei[e + i]], 1);     // dst degrees
    if (i < n) atomicAdd(&g_gcnt[batch[i]], 1);     // nodes per graph
}

// ---------------- single-pass decoupled-lookback exclusive scan --------------
// Also computes g_dinv, writes pre-scaled g_X8 = dinv*x, and zeroes g_cnt.
__global__ __launch_bounds__(1024)
void k_scan_lb(const float* __restrict__ x, int n, int e_total) {
    __shared__ int warp_sums[32];
    __shared__ int s_prefix;
    int b = blockIdx.x, tid = threadIdx.x, lane = tid & 31, wid = tid >> 5;
    int i = b * 1024 + tid;
    int v = (i < n) ? g_cnt[i] : 0;
    if (i < n) {
        float di = rsqrtf((float)(v + 1));          // +1 self loop
        g_dinv[i] = di;
        const float* xs = x + i * 7;
        float4* X84 = reinterpret_cast<float4*>(g_X8);
        X84[i * 2]     = make_float4(xs[0] * di, xs[1] * di, xs[2] * di, xs[3] * di);
        X84[i * 2 + 1] = make_float4(xs[4] * di, xs[5] * di, xs[6] * di, 0.f);
        g_cnt[i] = 0;                               // reset for next call
    }
    int xval = v;
    #pragma unroll
    for (int o = 1; o < 32; o <<= 1) {
        int y = __shfl_up_sync(0xffffffffu, xval, o);
        if (lane >= o) xval += y;
    }
    if (lane == 31) warp_sums[wid] = xval;
    __syncthreads();
    if (wid == 0) {
        int w = warp_sums[lane];
        #pragma unroll
        for (int o = 1; o < 32; o <<= 1) {
            int y = __shfl_up_sync(0xffffffffu, w, o);
            if (lane >= o) w += y;
        }
        warp_sums[lane] = w;
    }
    __syncthreads();
    int off = (wid > 0) ? warp_sums[wid - 1] : 0;
    int incl = xval + off;
    unsigned total = (unsigned)warp_sums[31];
    if (tid == 0) {
        if (b == 0) {
            atomicExch(&g_tilestate[0], (2u << 30) | total);
            s_prefix = 0;
        } else {
            atomicExch(&g_tilestate[b], (1u << 30) | total);
            unsigned pfx = 0;
            int p = b - 1;
            while (true) {
                unsigned st = atomicAdd(&g_tilestate[p], 0u);
                unsigned f = st >> 30;
                if (f == 0) continue;
                pfx += st & 0x3FFFFFFFu;
                if (f == 2) break;
                --p;
            }
            atomicExch(&g_tilestate[b], (2u << 30) | (total + pfx));
            s_prefix = (int)pfx;
        }
    }
    __syncthreads();
    int pfx = s_prefix;
    if (i < n) {
        int r = incl - v + pfx;
        g_rowptr[i] = r;
        g_pos[i] = r;
    }
    if (i == n - 1) g_rowptr[n] = e_total;
}

// CSR fill: src indices only. Also resets tilestate for the next call.
__global__ void k_fill(const int* __restrict__ ei, int e) {
    if (blockIdx.x == 0 && threadIdx.x < 64) g_tilestate[threadIdx.x] = 0;
    int i = blockIdx.x * blockDim.x + threadIdx.x;
    if (i < e) {
        int s = ei[i];
        int d = ei[e + i];
        int idx = atomicAdd(&g_pos[d], 1);
        g_csr_src[idx] = s;
    }
}

// ---------------- fused layer 1: gather-sum + transform + bias + relu --------
__global__ __launch_bounds__(256, 6)
void k_l1(const float* __restrict__ W1, const float* __restrict__ b1, int n) {
    int warp = (blockIdx.x * blockDim.x + threadIdx.x) >> 5;
    int lane = threadIdx.x & 31;
    if (warp >= n) return;
    int node = warp;
    const float4* X84 = reinterpret_cast<const float4*>(g_X8);
    float acc[7];
    if (lane == 0) {
        float4 lo = X84[node * 2], hi = X84[node * 2 + 1];
        acc[0] = lo.x; acc[1] = lo.y; acc[2] = lo.z; acc[3] = lo.w;
        acc[4] = hi.x; acc[5] = hi.y; acc[6] = hi.z;
    } else {
        #pragma unroll
        for (int f = 0; f < 7; ++f) acc[f] = 0.f;
    }
    int beg = g_rowptr[node], end = g_rowptr[node + 1];
    for (int e = beg + lane; e < end; e += 32) {
        int s = g_csr_src[e];
        float4 lo = X84[s * 2], hi = X84[s * 2 + 1];
        acc[0] += lo.x; acc[1] += lo.y; acc[2] += lo.z; acc[3] += lo.w;
        acc[4] += hi.x; acc[5] += hi.y; acc[6] += hi.z;
    }
    #pragma unroll
    for (int f = 0; f < 7; ++f)
        #pragma unroll
        for (int o = 16; o > 0; o >>= 1)
            acc[f] += __shfl_xor_sync(0xffffffffu, acc[f], o);
    float di = g_dinv[node];
    #pragma unroll
    for (int f = 0; f < 7; ++f) acc[f] *= di;
    int c = lane * 4;
    float4 r = *reinterpret_cast<const float4*>(&b1[c]);
    #pragma unroll
    for (int f = 0; f < 7; ++f) {
        float4 wv = *reinterpret_cast<const float4*>(&W1[f * 128 + c]);
        r.x = fmaf(acc[f], wv.x, r.x); r.y = fmaf(acc[f], wv.y, r.y);
        r.z = fmaf(acc[f], wv.z, r.z); r.w = fmaf(acc[f], wv.w, r.w);
    }
    r.x = fmaxf(r.x, 0.f); r.y = fmaxf(r.y, 0.f);
    r.z = fmaxf(r.z, 0.f); r.w = fmaxf(r.w, 0.f);
    *reinterpret_cast<float4*>(&g_H[node * 128 + c]) = r;
}

// -------- TF32 tensor-core GEMM: g_Th[r] = half( dinv[r] * (g_H[r] @ B) ) ----
template<int NOUT>
__global__ __launch_bounds__(256)
void k_gemm_tc(const float* __restrict__ Bw, int n) {
    constexpr int K = 128, KT = 32, BM = 128;
    constexpr int WN = NOUT / 2;
    constexpr int NF = WN / 8;
    constexpr int SBS = NOUT + 4;
    __shared__ uint32_t sA[BM][KT + 4];
    __shared__ uint32_t sB[KT][SBS];
    int tid = threadIdx.x;
    int w = tid >> 5, lane = tid & 31;
    int mw = w >> 1, nw = w & 1;
    int g = lane >> 2, t = lane & 3;
    int nodeBase = blockIdx.x * BM;
    float acc[2][NF][4];
    #pragma unroll
    for (int mf = 0; mf < 2; ++mf)
        #pragma unroll
        for (int nf = 0; nf < NF; ++nf)
            #pragma unroll
            for (int i = 0; i < 4; ++i) acc[mf][nf][i] = 0.f;

    for (int k0 = 0; k0 < K; k0 += KT) {
        #pragma unroll
        for (int it = 0; it < 4; ++it) {
            int idx = tid + it * 256;
            int r = idx >> 3, c4 = idx & 7;
            int nd = nodeBase + r;
            float4 v = make_float4(0.f, 0.f, 0.f, 0.f);
            if (nd < n) v = *reinterpret_cast<const float4*>(&g_H[nd * K + k0 + c4 * 4]);
            uint4 u = make_uint4(f2tf32(v.x), f2tf32(v.y), f2tf32(v.z), f2tf32(v.w));
            *reinterpret_cast<uint4*>(&sA[r][c4 * 4]) = u;
        }
        #pragma unroll
        for (int it = 0; it < KT * NOUT / 1024; ++it) {
            int idx = tid + it * 256;
            int r = idx / (NOUT / 4), c4 = idx % (NOUT / 4);
            float4 v = *reinterpret_cast<const float4*>(&Bw[(k0 + r) * NOUT + c4 * 4]);
            uint4 u = make_uint4(f2tf32(v.x), f2tf32(v.y), f2tf32(v.z), f2tf32(v.w));
            *reinterpret_cast<uint4*>(&sB[r][c4 * 4]) = u;
        }
        __syncthreads();
        #pragma unroll
        for (int ks = 0; ks < KT; ks += 8) {
            uint32_t a[2][4];
            #pragma unroll
            for (int mf = 0; mf < 2; ++mf) {
                int rb = mw * 32 + mf * 16;
                a[mf][0] = sA[rb + g][ks + t];
                a[mf][1] = sA[rb + g + 8][ks + t];
                a[mf][2] = sA[rb + g][ks + t + 4];
                a[mf][3] = sA[rb + g + 8][ks + t + 4];
            }
            #pragma unroll
            for (int nf = 0; nf < NF; ++nf) {
                int nb = nw * WN + nf * 8;
                uint32_t b0 = sB[ks + t][nb + g];
                uint32_t b1 = sB[ks + t + 4][nb + g];
                mma_tf32(acc[0][nf], a[0], b0, b1);
                mma_tf32(acc[1][nf], a[1], b0, b1);
            }
        }
        __syncthreads();
    }
    __half2* Th2 = reinterpret_cast<__half2*>(g_Th);
    #pragma unroll
    for (int mf = 0; mf < 2; ++mf) {
        int rowB = nodeBase + mw * 32 + mf * 16;
        int r0 = rowB + g, r1 = rowB + g + 8;
        float s0 = (r0 < n) ? g_dinv[r0] : 0.f;
        float s1 = (r1 < n) ? g_dinv[r1] : 0.f;
        #pragma unroll
        for (int nf = 0; nf < NF; ++nf) {
            int col = nw * WN + nf * 8 + t * 2;
            if (r0 < n)
                Th2[(r0 * NOUT + col) >> 1] =
                    __floats2half2_rn(acc[mf][nf][0] * s0, acc[mf][nf][1] * s0);
            if (r1 < n)
                Th2[(r1 * NOUT + col) >> 1] =
                    __floats2half2_rn(acc[mf][nf][2] * s1, acc[mf][nf][3] * s1);
        }
    }
}

// ------- sparse aggregation (fp16 gather): out = dinv_i*(T'[i]+sum) + b -----
// LPN = F/8 lanes per node; each lane covers 8 half features via one uint4.
template<int F, bool RELU, bool POOL, bool TO_H>
__global__ __launch_bounds__(256)
void k_agg(const float* __restrict__ bias, float* __restrict__ out,
           const int* __restrict__ batch, int n) {
    constexpr int LPN = F / 8;
    int gid = blockIdx.x * blockDim.x + threadIdx.x;
    int node = gid / LPN;
    int l = gid % LPN;
    if (node >= n) return;
    const uint4* T4 = reinterpret_cast<const uint4*>(g_Th);
    float acc[8];
    #pragma unroll
    for (int i = 0; i < 8; ++i) acc[i] = 0.f;
    h8_add(acc, T4[node * LPN + l]);               // self term (pre-scaled)
    int e = g_rowptr[node], end = g_rowptr[node + 1];
    for (; e + 3 < end; e += 4) {
        int s0 = g_csr_src[e],     s1 = g_csr_src[e + 1];
        int s2 = g_csr_src[e + 2], s3 = g_csr_src[e + 3];
        uint4 u0 = T4[s0 * LPN + l];
        uint4 u1 = T4[s1 * LPN + l];
        uint4 u2 = T4[s2 * LPN + l];
        uint4 u3 = T4[s3 * LPN + l];
        h8_add(acc, u0); h8_add(acc, u1); h8_add(acc, u2); h8_add(acc, u3);
    }
    for (; e < end; ++e) {
        h8_add(acc, T4[g_csr_src[e] * LPN + l]);
    }
    float di = g_dinv[node];
    float r[8];
    const float4* b4 = reinterpret_cast<const float4*>(bias);
    float4 bl = b4[l * 2], bh = b4[l * 2 + 1];
    r[0] = fmaf(di, acc[0], bl.x); r[1] = fmaf(di, acc[1], bl.y);
    r[2] = fmaf(di, acc[2], bl.z); r[3] = fmaf(di, acc[3], bl.w);
    r[4] = fmaf(di, acc[4], bh.x); r[5] = fmaf(di, acc[5], bh.y);
    r[6] = fmaf(di, acc[6], bh.z); r[7] = fmaf(di, acc[7], bh.w);
    if (RELU) {
        #pragma unroll
        for (int i = 0; i < 8; ++i) r[i] = fmaxf(r[i], 0.f);
    }
    float* dst = TO_H ? (g_H + node * F + l * 8) : (out + node * F + l * 8);
    *reinterpret_cast<float4*>(dst)     = make_float4(r[0], r[1], r[2], r[3]);
    *reinterpret_cast<float4*>(dst + 4) = make_float4(r[4], r[5], r[6], r[7]);
    if (POOL) {
        int gidx = batch[node];
        #pragma unroll
        for (int i = 0; i < 8; ++i)
            atomicAdd(&g_poolsum[gidx * F + l * 8 + i], r[i]);
    }
}

// pooled output + self-zero of poolsum/gcnt for the next call.
__global__ void k_pooldiv(float* __restrict__ out, int g) {
    int i = blockIdx.x * blockDim.x + threadIdx.x;
    bool act = i < g * OUTF;
    float c = 1.f, s = 0.f;
    if (act) {
        c = (float)g_gcnt[i / OUTF];
        s = g_poolsum[i];
    }
    __syncthreads();                    // all reads done before zeroing
    if (act) {
        out[i] = s / fmaxf(c, 1.f);
        g_poolsum[i] = 0.f;
        if ((i & (OUTF - 1)) == 0) g_gcnt[i / OUTF] = 0;
    }
}

// ---------------- launch ----------------
extern "C" void kernel_launch(void* const* d_in, const int* in_sizes, int n_in,
                              void* d_out, int out_size) {
    const float* x     = (const float*)d_in[0];
    const int*   ei    = (const int*)d_in[1];    // int32 (jax x64 disabled)
    const int*   batch = (const int*)d_in[2];    // int32
    const float* W1 = (const float*)d_in[3];
    const float* b1 = (const float*)d_in[4];
    const float* W2 = (const float*)d_in[5];
    const float* b2 = (const float*)d_in[6];
    const float* W3 = (const float*)d_in[7];
    const float* b3 = (const float*)d_in[8];
    float* out = (float*)d_out;

    int n = in_sizes[0] / 7;
    int e = in_sizes[1] / 2;
    int g = out_size / OUTF - n;
    if (g < 0) g = 0;

    const int T = 256;
    int nb = (n + 1023) / 1024;                         // scan tiles (<= 64)

    k_hist<<<(e + T - 1) / T, T>>>(ei, batch, e, n);    // 0
    k_scan_lb<<<nb, 1024>>>(x, n, e);                   // 1
    k_fill<<<(e + T - 1) / T, T>>>(ei, e);              // 2
    k_l1<<<(n * 32 + T - 1) / T, T>>>(W1, b1, n);       // 3  <- profiled launch

    k_gemm_tc<128><<<(n + 127) / 128, 256>>>(W2, n);    // 4
    k_agg<128, true, false, true><<<(n * 16 + T - 1) / T, T>>>(b2, nullptr, batch, n); // 5

    k_gemm_tc<64><<<(n + 127) / 128, 256>>>(W3, n);     // 6
    if (g > 0) {
        k_agg<64, false, true, false><<<(n * 8 + T - 1) / T, T>>>(b3, out, batch, n); // 7
        k_pooldiv<<<(g * OUTF + T - 1) / T, T>>>(out + (size_t)n * OUTF, g);          // 8
    } else {
        k_agg<64, false, false, false><<<(n * 8 + T - 1) / T, T>>>(b3, out, batch, n);
    }
}

// round 15
// speedup vs baseline: 1.2819x; 1.2819x over previous
#include <cuda_runtime.h>
#include <cuda_fp16.h>
#include <stdint.h>

// Problem constants (fixed by the dataset)
#define NMAX   50000
#define EMAX   800000
#define GMAX   64
#define HID    128
#define OUTF   64

// ---------------- device scratch (no allocations allowed) ----------------
// All zero at module load. Self-cleaning: every kernel that consumes
// call-scoped state zeroes it for the next call (g_cnt in k_scan_lb,
// g_tilestate in k_fill, g_poolsum/g_gcnt in k_pooldiv).
__device__ int                    g_cnt[NMAX];
__device__ unsigned int           g_tilestate[64];   // lookback scan state
__device__ int                    g_rowptr[NMAX + 1];
__device__ int                    g_pos[NMAX];
__device__ int                    g_csr_src[EMAX];
__device__ float                  g_dinv[NMAX];
__device__ __align__(16) float    g_X8[NMAX * 8];    // dinv[i]*x[i], padded to 8
__device__ __align__(16) __half   g_Th[NMAX * HID];  // dinv-scaled GEMM outputs (fp16)
__device__ __align__(16) float    g_H[NMAX * HID];   // activations (fp32)
__device__ float                  g_poolsum[GMAX * OUTF];
__device__ int                    g_gcnt[GMAX];

// ---------------- tf32 helpers ----------------
__device__ __forceinline__ uint32_t f2tf32(float f) {
    uint32_t r;
    asm("cvt.rna.tf32.f32 %0, %1;" : "=r"(r) : "f"(f));
    return r;
}
__device__ __forceinline__ void mma_tf32(float* c, const uint32_t* a,
                                         uint32_t b0, uint32_t b1) {
    asm("mma.sync.aligned.m16n8k8.row.col.f32.tf32.tf32.f32 "
        "{%0,%1,%2,%3}, {%4,%5,%6,%7}, {%8,%9}, {%0,%1,%2,%3};"
        : "+f"(c[0]), "+f"(c[1]), "+f"(c[2]), "+f"(c[3])
        : "r"(a[0]), "r"(a[1]), "r"(a[2]), "r"(a[3]), "r"(b0), "r"(b1));
}

// unpack uint2 (4 halves) and add into 4 fp32 accumulators
__device__ __forceinline__ void h4_add(float* acc, uint2 u) {
    const __half2* h = reinterpret_cast<const __half2*>(&u);
    float2 f0 = __half22float2(h[0]);
    float2 f1 = __half22float2(h[1]);
    acc[0] += f0.x; acc[1] += f0.y; acc[2] += f1.x; acc[3] += f1.y;
}

// ---------------- setup: degree + graph-size histograms ----------------
__global__ void k_hist(const int* __restrict__ ei, const int* __restrict__ batch,
                       int e, int n) {
    int i = blockIdx.x * blockDim.x + threadIdx.x;
    if (i < e) atomicAdd(&g_cnt[ei[e + i]], 1);     // dst degrees
    if (i < n) atomicAdd(&g_gcnt[batch[i]], 1);     // nodes per graph
}

// ---------------- single-pass decoupled-lookback exclusive scan --------------
// Also computes g_dinv, writes pre-scaled g_X8 = dinv*x, and zeroes g_cnt.
__global__ __launch_bounds__(1024)
void k_scan_lb(const float* __restrict__ x, int n, int e_total) {
    __shared__ int warp_sums[32];
    __shared__ int s_prefix;
    int b = blockIdx.x, tid = threadIdx.x, lane = tid & 31, wid = tid >> 5;
    int i = b * 1024 + tid;
    int v = (i < n) ? g_cnt[i] : 0;
    if (i < n) {
        float di = rsqrtf((float)(v + 1));          // +1 self loop
        g_dinv[i] = di;
        const float* xs = x + i * 7;
        float4* X84 = reinterpret_cast<float4*>(g_X8);
        X84[i * 2]     = make_float4(xs[0] * di, xs[1] * di, xs[2] * di, xs[3] * di);
        X84[i * 2 + 1] = make_float4(xs[4] * di, xs[5] * di, xs[6] * di, 0.f);
        g_cnt[i] = 0;                               // reset for next call
    }
    int xval = v;
    #pragma unroll
    for (int o = 1; o < 32; o <<= 1) {
        int y = __shfl_up_sync(0xffffffffu, xval, o);
        if (lane >= o) xval += y;
    }
    if (lane == 31) warp_sums[wid] = xval;
    __syncthreads();
    if (wid == 0) {
        int w = warp_sums[lane];
        #pragma unroll
        for (int o = 1; o < 32; o <<= 1) {
            int y = __shfl_up_sync(0xffffffffu, w, o);
            if (lane >= o) w += y;
        }
        warp_sums[lane] = w;
    }
    __syncthreads();
    int off = (wid > 0) ? warp_sums[wid - 1] : 0;
    int incl = xval + off;
    unsigned total = (unsigned)warp_sums[31];
    if (tid == 0) {
        if (b == 0) {
            atomicExch(&g_tilestate[0], (2u << 30) | total);
            s_prefix = 0;
        } else {
            atomicExch(&g_tilestate[b], (1u << 30) | total);
            unsigned pfx = 0;
            int p = b - 1;
            while (true) {
                unsigned st = atomicAdd(&g_tilestate[p], 0u);
                unsigned f = st >> 30;
                if (f == 0) continue;
                pfx += st & 0x3FFFFFFFu;
                if (f == 2) break;
                --p;
            }
            atomicExch(&g_tilestate[b], (2u << 30) | (total + pfx));
            s_prefix = (int)pfx;
        }
    }
    __syncthreads();
    int pfx = s_prefix;
    if (i < n) {
        int r = incl - v + pfx;
        g_rowptr[i] = r;
        g_pos[i] = r;
    }
    if (i == n - 1) g_rowptr[n] = e_total;
}

// CSR fill: src indices only. Also resets tilestate for the next call.
__global__ void k_fill(const int* __restrict__ ei, int e) {
    if (blockIdx.x == 0 && threadIdx.x < 64) g_tilestate[threadIdx.x] = 0;
    int i = blockIdx.x * blockDim.x + threadIdx.x;
    if (i < e) {
        int s = ei[i];
        int d = ei[e + i];
        int idx = atomicAdd(&g_pos[d], 1);
        g_csr_src[idx] = s;
    }
}

// ---------------- fused layer 1: gather-sum + transform + bias + relu --------
__global__ __launch_bounds__(256, 6)
void k_l1(const float* __restrict__ W1, const float* __restrict__ b1, int n) {
    int warp = (blockIdx.x * blockDim.x + threadIdx.x) >> 5;
    int lane = threadIdx.x & 31;
    if (warp >= n) return;
    int node = warp;
    const float4* X84 = reinterpret_cast<const float4*>(g_X8);
    float acc[7];
    if (lane == 0) {
        float4 lo = X84[node * 2], hi = X84[node * 2 + 1];
        acc[0] = lo.x; acc[1] = lo.y; acc[2] = lo.z; acc[3] = lo.w;
        acc[4] = hi.x; acc[5] = hi.y; acc[6] = hi.z;
    } else {
        #pragma unroll
        for (int f = 0; f < 7; ++f) acc[f] = 0.f;
    }
    int beg = g_rowptr[node], end = g_rowptr[node + 1];
    for (int e = beg + lane; e < end; e += 32) {
        int s = g_csr_src[e];
        float4 lo = X84[s * 2], hi = X84[s * 2 + 1];
        acc[0] += lo.x; acc[1] += lo.y; acc[2] += lo.z; acc[3] += lo.w;
        acc[4] += hi.x; acc[5] += hi.y; acc[6] += hi.z;
    }
    #pragma unroll
    for (int f = 0; f < 7; ++f)
        #pragma unroll
        for (int o = 16; o > 0; o >>= 1)
            acc[f] += __shfl_xor_sync(0xffffffffu, acc[f], o);
    float di = g_dinv[node];
    #pragma unroll
    for (int f = 0; f < 7; ++f) acc[f] *= di;
    int c = lane * 4;
    float4 r = *reinterpret_cast<const float4*>(&b1[c]);
    #pragma unroll
    for (int f = 0; f < 7; ++f) {
        float4 wv = *reinterpret_cast<const float4*>(&W1[f * 128 + c]);
        r.x = fmaf(acc[f], wv.x, r.x); r.y = fmaf(acc[f], wv.y, r.y);
        r.z = fmaf(acc[f], wv.z, r.z); r.w = fmaf(acc[f], wv.w, r.w);
    }
    r.x = fmaxf(r.x, 0.f); r.y = fmaxf(r.y, 0.f);
    r.z = fmaxf(r.z, 0.f); r.w = fmaxf(r.w, 0.f);
    *reinterpret_cast<float4*>(&g_H[node * 128 + c]) = r;
}

// -------- TF32 tensor-core GEMM: g_Th[r] = half( dinv[r] * (g_H[r] @ B) ) ----
template<int NOUT>
__global__ __launch_bounds__(256)
void k_gemm_tc(const float* __restrict__ Bw, int n) {
    constexpr int K = 128, KT = 32, BM = 128;
    constexpr int WN = NOUT / 2;
    constexpr int NF = WN / 8;
    constexpr int SBS = NOUT + 4;
    __shared__ uint32_t sA[BM][KT + 4];
    __shared__ uint32_t sB[KT][SBS];
    int tid = threadIdx.x;
    int w = tid >> 5, lane = tid & 31;
    int mw = w >> 1, nw = w & 1;
    int g = lane >> 2, t = lane & 3;
    int nodeBase = blockIdx.x * BM;
    float acc[2][NF][4];
    #pragma unroll
    for (int mf = 0; mf < 2; ++mf)
        #pragma unroll
        for (int nf = 0; nf < NF; ++nf)
            #pragma unroll
            for (int i = 0; i < 4; ++i) acc[mf][nf][i] = 0.f;

    for (int k0 = 0; k0 < K; k0 += KT) {
        #pragma unroll
        for (int it = 0; it < 4; ++it) {
            int idx = tid + it * 256;
            int r = idx >> 3, c4 = idx & 7;
            int nd = nodeBase + r;
            float4 v = make_float4(0.f, 0.f, 0.f, 0.f);
            if (nd < n) v = *reinterpret_cast<const float4*>(&g_H[nd * K + k0 + c4 * 4]);
            uint4 u = make_uint4(f2tf32(v.x), f2tf32(v.y), f2tf32(v.z), f2tf32(v.w));
            *reinterpret_cast<uint4*>(&sA[r][c4 * 4]) = u;
        }
        #pragma unroll
        for (int it = 0; it < KT * NOUT / 1024; ++it) {
            int idx = tid + it * 256;
            int r = idx / (NOUT / 4), c4 = idx % (NOUT / 4);
            float4 v = *reinterpret_cast<const float4*>(&Bw[(k0 + r) * NOUT + c4 * 4]);
            uint4 u = make_uint4(f2tf32(v.x), f2tf32(v.y), f2tf32(v.z), f2tf32(v.w));
            *reinterpret_cast<uint4*>(&sB[r][c4 * 4]) = u;
        }
        __syncthreads();
        #pragma unroll
        for (int ks = 0; ks < KT; ks += 8) {
            uint32_t a[2][4];
            #pragma unroll
            for (int mf = 0; mf < 2; ++mf) {
                int rb = mw * 32 + mf * 16;
                a[mf][0] = sA[rb + g][ks + t];
                a[mf][1] = sA[rb + g + 8][ks + t];
                a[mf][2] = sA[rb + g][ks + t + 4];
                a[mf][3] = sA[rb + g + 8][ks + t + 4];
            }
            #pragma unroll
            for (int nf = 0; nf < NF; ++nf) {
                int nb = nw * WN + nf * 8;
                uint32_t b0 = sB[ks + t][nb + g];
                uint32_t b1 = sB[ks + t + 4][nb + g];
                mma_tf32(acc[0][nf], a[0], b0, b1);
                mma_tf32(acc[1][nf], a[1], b0, b1);
            }
        }
        __syncthreads();
    }
    __half2* Th2 = reinterpret_cast<__half2*>(g_Th);
    #pragma unroll
    for (int mf = 0; mf < 2; ++mf) {
        int rowB = nodeBase + mw * 32 + mf * 16;
        int r0 = rowB + g, r1 = rowB + g + 8;
        float s0 = (r0 < n) ? g_dinv[r0] : 0.f;
        float s1 = (r1 < n) ? g_dinv[r1] : 0.f;
        #pragma unroll
        for (int nf = 0; nf < NF; ++nf) {
            int col = nw * WN + nf * 8 + t * 2;
            if (r0 < n)
                Th2[(r0 * NOUT + col) >> 1] =
                    __floats2half2_rn(acc[mf][nf][0] * s0, acc[mf][nf][1] * s0);
            if (r1 < n)
                Th2[(r1 * NOUT + col) >> 1] =
                    __floats2half2_rn(acc[mf][nf][2] * s1, acc[mf][nf][3] * s1);
        }
    }
}

// ------- sparse aggregation (fp16 gather): out = dinv_i*(T'[i]+sum) + b -----
// LPN = F/4 lanes per node (same concurrency as fp32 version); each lane
// covers 4 half features via one uint2 (8B). F=128: full warp per node.
template<int F, bool RELU, bool POOL, bool TO_H>
__global__ __launch_bounds__(256)
void k_agg(const float* __restrict__ bias, float* __restrict__ out,
           const int* __restrict__ batch, int n) {
    constexpr int LPN = F / 4;
    int gid = blockIdx.x * blockDim.x + threadIdx.x;
    int node = gid / LPN;
    int l = gid % LPN;
    if (node >= n) return;
    const uint2* T2 = reinterpret_cast<const uint2*>(g_Th);
    float acc[4];
    #pragma unroll
    for (int i = 0; i < 4; ++i) acc[i] = 0.f;
    h4_add(acc, T2[node * LPN + l]);               // self term (pre-scaled)
    int e = g_rowptr[node], end = g_rowptr[node + 1];
    for (; e + 3 < end; e += 4) {
        int s0 = g_csr_src[e],     s1 = g_csr_src[e + 1];
        int s2 = g_csr_src[e + 2], s3 = g_csr_src[e + 3];
        uint2 u0 = T2[s0 * LPN + l];
        uint2 u1 = T2[s1 * LPN + l];
        uint2 u2 = T2[s2 * LPN + l];
        uint2 u3 = T2[s3 * LPN + l];
        h4_add(acc, u0); h4_add(acc, u1); h4_add(acc, u2); h4_add(acc, u3);
    }
    for (; e < end; ++e) {
        h4_add(acc, T2[g_csr_src[e] * LPN + l]);
    }
    float di = g_dinv[node];
    float4 b = reinterpret_cast<const float4*>(bias)[l];
    float4 r;
    r.x = fmaf(di, acc[0], b.x); r.y = fmaf(di, acc[1], b.y);
    r.z = fmaf(di, acc[2], b.z); r.w = fmaf(di, acc[3], b.w);
    if (RELU) {
        r.x = fmaxf(r.x, 0.f); r.y = fmaxf(r.y, 0.f);
        r.z = fmaxf(r.z, 0.f); r.w = fmaxf(r.w, 0.f);
    }
    if (TO_H)
        reinterpret_cast<float4*>(g_H)[node * LPN + l] = r;
    else
        reinterpret_cast<float4*>(out)[node * LPN + l] = r;
    if (POOL) {
        int gidx = batch[node];
        atomicAdd(&g_poolsum[gidx * F + l * 4 + 0], r.x);
        atomicAdd(&g_poolsum[gidx * F + l * 4 + 1], r.y);
        atomicAdd(&g_poolsum[gidx * F + l * 4 + 2], r.z);
        atomicAdd(&g_poolsum[gidx * F + l * 4 + 3], r.w);
    }
}

// pooled output + self-zero of poolsum/gcnt for the next call.
__global__ void k_pooldiv(float* __restrict__ out, int g) {
    int i = blockIdx.x * blockDim.x + threadIdx.x;
    bool act = i < g * OUTF;
    float c = 1.f, s = 0.f;
    if (act) {
        c = (float)g_gcnt[i / OUTF];
        s = g_poolsum[i];
    }
    __syncthreads();                    // all reads done before zeroing
    if (act) {
        out[i] = s / fmaxf(c, 1.f);
        g_poolsum[i] = 0.f;
        if ((i & (OUTF - 1)) == 0) g_gcnt[i / OUTF] = 0;
    }
}

// ---------------- launch ----------------
extern "C" void kernel_launch(void* const* d_in, const int* in_sizes, int n_in,
                              void* d_out, int out_size) {
    const float* x     = (const float*)d_in[0];
    const int*   ei    = (const int*)d_in[1];    // int32 (jax x64 disabled)
    const int*   batch = (const int*)d_in[2];    // int32
    const float* W1 = (const float*)d_in[3];
    const float* b1 = (const float*)d_in[4];
    const float* W2 = (const float*)d_in[5];
    const float* b2 = (const float*)d_in[6];
    const float* W3 = (const float*)d_in[7];
    const float* b3 = (const float*)d_in[8];
    float* out = (float*)d_out;

    int n = in_sizes[0] / 7;
    int e = in_sizes[1] / 2;
    int g = out_size / OUTF - n;
    if (g < 0) g = 0;

    const int T = 256;
    int nb = (n + 1023) / 1024;                         // scan tiles (<= 64)

    k_hist<<<(e + T - 1) / T, T>>>(ei, batch, e, n);    // 0
    k_scan_lb<<<nb, 1024>>>(x, n, e);                   // 1
    k_fill<<<(e + T - 1) / T, T>>>(ei, e);              // 2
    k_l1<<<(n * 32 + T - 1) / T, T>>>(W1, b1, n);       // 3  <- profiled launch

    k_gemm_tc<128><<<(n + 127) / 128, 256>>>(W2, n);    // 4
    k_agg<128, true, false, true><<<(n * 32 + T - 1) / T, T>>>(b2, nullptr, batch, n); // 5

    k_gemm_tc<64><<<(n + 127) / 128, 256>>>(W3, n);     // 6
    if (g > 0) {
        k_agg<64, false, true, false><<<(n * 16 + T - 1) / T, T>>>(b3, out, batch, n); // 7
        k_pooldiv<<<(g * OUTF + T - 1) / T, T>>>(out + (size_t)n * OUTF, g);           // 8
    } else {
        k_agg<64, false, false, false><<<(n * 16 + T - 1) / T, T>>>(b3, out, batch, n);
    }
}

// round 16
// speedup vs baseline: 1.3125x; 1.0239x over previous
#include <cuda_runtime.h>
#include <cuda_fp16.h>
#include <stdint.h>

// Problem constants (fixed by the dataset)
#define NMAX   50000
#define EMAX   800000
#define GMAX   64
#define HID    128
#define OUTF   64

// ---------------- device scratch (no allocations allowed) ----------------
// All zero at module load. Self-cleaning: every kernel that consumes
// call-scoped state zeroes it for the next call (g_cnt in k_scan_lb,
// g_tilestate in k_fill, g_poolsum/g_gcnt in k_pooldiv).
__device__ int                    g_cnt[NMAX];
__device__ unsigned int           g_tilestate[64];   // lookback scan state
__device__ int                    g_rowptr[NMAX + 1];
__device__ int                    g_pos[NMAX];
__device__ __align__(16) int      g_csr_src[EMAX];
__device__ float                  g_dinv[NMAX];
__device__ __align__(16) __half   g_Xh[NMAX * 8];    // dinv[i]*x[i] fp16, padded to 8
__device__ __align__(16) __half   g_Th[NMAX * HID];  // dinv-scaled GEMM outputs (fp16)
__device__ __align__(16) float    g_H[NMAX * HID];   // activations (fp32)
__device__ float                  g_poolsum[GMAX * OUTF];
__device__ int                    g_gcnt[GMAX];

// ---------------- tf32 helpers ----------------
__device__ __forceinline__ uint32_t f2tf32(float f) {
    uint32_t r;
    asm("cvt.rna.tf32.f32 %0, %1;" : "=r"(r) : "f"(f));
    return r;
}
__device__ __forceinline__ void mma_tf32(float* c, const uint32_t* a,
                                         uint32_t b0, uint32_t b1) {
    asm("mma.sync.aligned.m16n8k8.row.col.f32.tf32.tf32.f32 "
        "{%0,%1,%2,%3}, {%4,%5,%6,%7}, {%8,%9}, {%0,%1,%2,%3};"
        : "+f"(c[0]), "+f"(c[1]), "+f"(c[2]), "+f"(c[3])
        : "r"(a[0]), "r"(a[1]), "r"(a[2]), "r"(a[3]), "r"(b0), "r"(b1));
}

// unpack uint2 (4 halves) and add into 4 fp32 accumulators
__device__ __forceinline__ void h4_add(float* acc, uint2 u) {
    const __half2* h = reinterpret_cast<const __half2*>(&u);
    float2 f0 = __half22float2(h[0]);
    float2 f1 = __half22float2(h[1]);
    acc[0] += f0.x; acc[1] += f0.y; acc[2] += f1.x; acc[3] += f1.y;
}

// unpack uint4 (8 halves) and add first 7 into fp32 accumulators
__device__ __forceinline__ void h7_add(float* acc, uint4 u) {
    const __half2* h = reinterpret_cast<const __half2*>(&u);
    float2 f0 = __half22float2(h[0]);
    float2 f1 = __half22float2(h[1]);
    float2 f2 = __half22float2(h[2]);
    float2 f3 = __half22float2(h[3]);
    acc[0] += f0.x; acc[1] += f0.y; acc[2] += f1.x; acc[3] += f1.y;
    acc[4] += f2.x; acc[5] += f2.y; acc[6] += f3.x;
}

// ---------------- setup: degree + graph-size histograms ----------------
__global__ void k_hist(const int* __restrict__ ei, const int* __restrict__ batch,
                       int e, int n) {
    int i = blockIdx.x * blockDim.x + threadIdx.x;
    if (i < e) atomicAdd(&g_cnt[ei[e + i]], 1);     // dst degrees
    if (i < n) atomicAdd(&g_gcnt[batch[i]], 1);     // nodes per graph
}

// ---------------- single-pass decoupled-lookback exclusive scan --------------
// Also computes g_dinv, writes pre-scaled fp16 g_Xh = dinv*x, zeroes g_cnt.
__global__ __launch_bounds__(1024)
void k_scan_lb(const float* __restrict__ x, int n, int e_total) {
    __shared__ int warp_sums[32];
    __shared__ int s_prefix;
    int b = blockIdx.x, tid = threadIdx.x, lane = tid & 31, wid = tid >> 5;
    int i = b * 1024 + tid;
    int v = (i < n) ? g_cnt[i] : 0;
    if (i < n) {
        float di = rsqrtf((float)(v + 1));          // +1 self loop
        g_dinv[i] = di;
        const float* xs = x + i * 7;
        __half2 h0 = __floats2half2_rn(xs[0] * di, xs[1] * di);
        __half2 h1 = __floats2half2_rn(xs[2] * di, xs[3] * di);
        __half2 h2 = __floats2half2_rn(xs[4] * di, xs[5] * di);
        __half2 h3 = __floats2half2_rn(xs[6] * di, 0.f);
        uint4 u;
        u.x = *reinterpret_cast<uint32_t*>(&h0);
        u.y = *reinterpret_cast<uint32_t*>(&h1);
        u.z = *reinterpret_cast<uint32_t*>(&h2);
        u.w = *reinterpret_cast<uint32_t*>(&h3);
        reinterpret_cast<uint4*>(g_Xh)[i] = u;
        g_cnt[i] = 0;                               // reset for next call
    }
    int xval = v;
    #pragma unroll
    for (int o = 1; o < 32; o <<= 1) {
        int y = __shfl_up_sync(0xffffffffu, xval, o);
        if (lane >= o) xval += y;
    }
    if (lane == 31) warp_sums[wid] = xval;
    __syncthreads();
    if (wid == 0) {
        int w = warp_sums[lane];
        #pragma unroll
        for (int o = 1; o < 32; o <<= 1) {
            int y = __shfl_up_sync(0xffffffffu, w, o);
            if (lane >= o) w += y;
        }
        warp_sums[lane] = w;
    }
    __syncthreads();
    int off = (wid > 0) ? warp_sums[wid - 1] : 0;
    int incl = xval + off;
    unsigned total = (unsigned)warp_sums[31];
    if (tid == 0) {
        if (b == 0) {
            atomicExch(&g_tilestate[0], (2u << 30) | total);
            s_prefix = 0;
        } else {
            atomicExch(&g_tilestate[b], (1u << 30) | total);
            unsigned pfx = 0;
            int p = b - 1;
            while (true) {
                unsigned st = atomicAdd(&g_tilestate[p], 0u);
                unsigned f = st >> 30;
                if (f == 0) continue;
                pfx += st & 0x3FFFFFFFu;
                if (f == 2) break;
                --p;
            }
            atomicExch(&g_tilestate[b], (2u << 30) | (total + pfx));
            s_prefix = (int)pfx;
        }
    }
    __syncthreads();
    int pfx = s_prefix;
    if (i < n) {
        int r = incl - v + pfx;
        g_rowptr[i] = r;
        g_pos[i] = r;
    }
    if (i == n - 1) g_rowptr[n] = e_total;
}

// CSR fill: src indices only. Also resets tilestate for the next call.
__global__ void k_fill(const int* __restrict__ ei, int e) {
    if (blockIdx.x == 0 && threadIdx.x < 64) g_tilestate[threadIdx.x] = 0;
    int i = blockIdx.x * blockDim.x + threadIdx.x;
    if (i < e) {
        int s = ei[i];
        int d = ei[e + i];
        int idx = atomicAdd(&g_pos[d], 1);
        g_csr_src[idx] = s;
    }
}

// ---------------- fused layer 1: gather-sum + transform + bias + relu --------
// warp per node; ONE uint4 (8 fp16) gather per edge.
__global__ __launch_bounds__(256, 6)
void k_l1(const float* __restrict__ W1, const float* __restrict__ b1, int n) {
    int warp = (blockIdx.x * blockDim.x + threadIdx.x) >> 5;
    int lane = threadIdx.x & 31;
    if (warp >= n) return;
    int node = warp;
    const uint4* Xh4 = reinterpret_cast<const uint4*>(g_Xh);
    float acc[7];
    #pragma unroll
    for (int f = 0; f < 7; ++f) acc[f] = 0.f;
    if (lane == 0) h7_add(acc, Xh4[node]);          // self term (pre-scaled)
    int beg = g_rowptr[node], end = g_rowptr[node + 1];
    for (int e = beg + lane; e < end; e += 32) {
        h7_add(acc, Xh4[g_csr_src[e]]);
    }
    #pragma unroll
    for (int f = 0; f < 7; ++f)
        #pragma unroll
        for (int o = 16; o > 0; o >>= 1)
            acc[f] += __shfl_xor_sync(0xffffffffu, acc[f], o);
    float di = g_dinv[node];
    #pragma unroll
    for (int f = 0; f < 7; ++f) acc[f] *= di;
    int c = lane * 4;
    float4 r = *reinterpret_cast<const float4*>(&b1[c]);
    #pragma unroll
    for (int f = 0; f < 7; ++f) {
        float4 wv = *reinterpret_cast<const float4*>(&W1[f * 128 + c]);
        r.x = fmaf(acc[f], wv.x, r.x); r.y = fmaf(acc[f], wv.y, r.y);
        r.z = fmaf(acc[f], wv.z, r.z); r.w = fmaf(acc[f], wv.w, r.w);
    }
    r.x = fmaxf(r.x, 0.f); r.y = fmaxf(r.y, 0.f);
    r.z = fmaxf(r.z, 0.f); r.w = fmaxf(r.w, 0.f);
    *reinterpret_cast<float4*>(&g_H[node * 128 + c]) = r;
}

// -------- TF32 tensor-core GEMM: g_Th[r] = half( dinv[r] * (g_H[r] @ B) ) ----
template<int NOUT>
__global__ __launch_bounds__(256)
void k_gemm_tc(const float* __restrict__ Bw, int n) {
    constexpr int K = 128, KT = 32, BM = 128;
    constexpr int WN = NOUT / 2;
    constexpr int NF = WN / 8;
    constexpr int SBS = NOUT + 4;
    __shared__ uint32_t sA[BM][KT + 4];
    __shared__ uint32_t sB[KT][SBS];
    int tid = threadIdx.x;
    int w = tid >> 5, lane = tid & 31;
    int mw = w >> 1, nw = w & 1;
    int g = lane >> 2, t = lane & 3;
    int nodeBase = blockIdx.x * BM;
    float acc[2][NF][4];
    #pragma unroll
    for (int mf = 0; mf < 2; ++mf)
        #pragma unroll
        for (int nf = 0; nf < NF; ++nf)
            #pragma unroll
            for (int i = 0; i < 4; ++i) acc[mf][nf][i] = 0.f;

    for (int k0 = 0; k0 < K; k0 += KT) {
        #pragma unroll
        for (int it = 0; it < 4; ++it) {
            int idx = tid + it * 256;
            int r = idx >> 3, c4 = idx & 7;
            int nd = nodeBase + r;
            float4 v = make_float4(0.f, 0.f, 0.f, 0.f);
            if (nd < n) v = *reinterpret_cast<const float4*>(&g_H[nd * K + k0 + c4 * 4]);
            uint4 u = make_uint4(f2tf32(v.x), f2tf32(v.y), f2tf32(v.z), f2tf32(v.w));
            *reinterpret_cast<uint4*>(&sA[r][c4 * 4]) = u;
        }
        #pragma unroll
        for (int it = 0; it < KT * NOUT / 1024; ++it) {
            int idx = tid + it * 256;
            int r = idx / (NOUT / 4), c4 = idx % (NOUT / 4);
            float4 v = *reinterpret_cast<const float4*>(&Bw[(k0 + r) * NOUT + c4 * 4]);
            uint4 u = make_uint4(f2tf32(v.x), f2tf32(v.y), f2tf32(v.z), f2tf32(v.w));
            *reinterpret_cast<uint4*>(&sB[r][c4 * 4]) = u;
        }
        __syncthreads();
        #pragma unroll
        for (int ks = 0; ks < KT; ks += 8) {
            uint32_t a[2][4];
            #pragma unroll
            for (int mf = 0; mf < 2; ++mf) {
                int rb = mw * 32 + mf * 16;
                a[mf][0] = sA[rb + g][ks + t];
                a[mf][1] = sA[rb + g + 8][ks + t];
                a[mf][2] = sA[rb + g][ks + t + 4];
                a[mf][3] = sA[rb + g + 8][ks + t + 4];
            }
            #pragma unroll
            for (int nf = 0; nf < NF; ++nf) {
                int nb = nw * WN + nf * 8;
                uint32_t b0 = sB[ks + t][nb + g];
                uint32_t b1 = sB[ks + t + 4][nb + g];
                mma_tf32(acc[0][nf], a[0], b0, b1);
                mma_tf32(acc[1][nf], a[1], b0, b1);
            }
        }
        __syncthreads();
    }
    __half2* Th2 = reinterpret_cast<__half2*>(g_Th);
    #pragma unroll
    for (int mf = 0; mf < 2; ++mf) {
        int rowB = nodeBase + mw * 32 + mf * 16;
        int r0 = rowB + g, r1 = rowB + g + 8;
        float s0 = (r0 < n) ? g_dinv[r0] : 0.f;
        float s1 = (r1 < n) ? g_dinv[r1] : 0.f;
        #pragma unroll
        for (int nf = 0; nf < NF; ++nf) {
            int col = nw * WN + nf * 8 + t * 2;
            if (r0 < n)
                Th2[(r0 * NOUT + col) >> 1] =
                    __floats2half2_rn(acc[mf][nf][0] * s0, acc[mf][nf][1] * s0);
            if (r1 < n)
                Th2[(r1 * NOUT + col) >> 1] =
                    __floats2half2_rn(acc[mf][nf][2] * s1, acc[mf][nf][3] * s1);
        }
    }
}

// ------- sparse aggregation (fp16 gather): out = dinv_i*(T'[i]+sum) + b -----
// LPN = F/4 lanes per node; each lane one uint2 (4 halves). Index loads
// batched 4-at-a-time via aligned int4 (one broadcast LDG per 4 edges).
template<int F, bool RELU, bool POOL, bool TO_H>
__global__ __launch_bounds__(256)
void k_agg(const float* __restrict__ bias, float* __restrict__ out,
           const int* __restrict__ batch, int n) {
    constexpr int LPN = F / 4;
    int gid = blockIdx.x * blockDim.x + threadIdx.x;
    int node = gid / LPN;
    int l = gid % LPN;
    if (node >= n) return;
    const uint2* T2 = reinterpret_cast<const uint2*>(g_Th);
    float acc[4];
    #pragma unroll
    for (int i = 0; i < 4; ++i) acc[i] = 0.f;
    h4_add(acc, T2[node * LPN + l]);               // self term (pre-scaled)
    int e = g_rowptr[node], end = g_rowptr[node + 1];
    // scalar head until e is 4-aligned (uniform per node group)
    while ((e & 3) && e < end) {
        h4_add(acc, T2[g_csr_src[e] * LPN + l]);
        ++e;
    }
    // main: one int4 index load per 4 edges
    for (; e + 3 < end; e += 4) {
        int4 s4 = *reinterpret_cast<const int4*>(&g_csr_src[e]);
        uint2 u0 = T2[s4.x * LPN + l];
        uint2 u1 = T2[s4.y * LPN + l];
        uint2 u2 = T2[s4.z * LPN + l];
        uint2 u3 = T2[s4.w * LPN + l];
        h4_add(acc, u0); h4_add(acc, u1); h4_add(acc, u2); h4_add(acc, u3);
    }
    for (; e < end; ++e) {
        h4_add(acc, T2[g_csr_src[e] * LPN + l]);
    }
    float di = g_dinv[node];
    float4 b = reinterpret_cast<const float4*>(bias)[l];
    float4 r;
    r.x = fmaf(di, acc[0], b.x); r.y = fmaf(di, acc[1], b.y);
    r.z = fmaf(di, acc[2], b.z); r.w = fmaf(di, acc[3], b.w);
    if (RELU) {
        r.x = fmaxf(r.x, 0.f); r.y = fmaxf(r.y, 0.f);
        r.z = fmaxf(r.z, 0.f); r.w = fmaxf(r.w, 0.f);
    }
    if (TO_H)
        reinterpret_cast<float4*>(g_H)[node * LPN + l] = r;
    else
        reinterpret_cast<float4*>(out)[node * LPN + l] = r;
    if (POOL) {
        int gidx = batch[node];
        atomicAdd(&g_poolsum[gidx * F + l * 4 + 0], r.x);
        atomicAdd(&g_poolsum[gidx * F + l * 4 + 1], r.y);
        atomicAdd(&g_poolsum[gidx * F + l * 4 + 2], r.z);
        atomicAdd(&g_poolsum[gidx * F + l * 4 + 3], r.w);
    }
}

// pooled output + self-zero of poolsum/gcnt for the next call.
__global__ void k_pooldiv(float* __restrict__ out, int g) {
    int i = blockIdx.x * blockDim.x + threadIdx.x;
    bool act = i < g * OUTF;
    float c = 1.f, s = 0.f;
    if (act) {
        c = (float)g_gcnt[i / OUTF];
        s = g_poolsum[i];
    }
    __syncthreads();                    // all reads done before zeroing
    if (act) {
        out[i] = s / fmaxf(c, 1.f);
        g_poolsum[i] = 0.f;
        if ((i & (OUTF - 1)) == 0) g_gcnt[i / OUTF] = 0;
    }
}

// ---------------- launch ----------------
extern "C" void kernel_launch(void* const* d_in, const int* in_sizes, int n_in,
                              void* d_out, int out_size) {
    const float* x     = (const float*)d_in[0];
    const int*   ei    = (const int*)d_in[1];    // int32 (jax x64 disabled)
    const int*   batch = (const int*)d_in[2];    // int32
    const float* W1 = (const float*)d_in[3];
    const float* b1 = (const float*)d_in[4];
    const float* W2 = (const float*)d_in[5];
    const float* b2 = (const float*)d_in[6];
    const float* W3 = (const float*)d_in[7];
    const float* b3 = (const float*)d_in[8];
    float* out = (float*)d_out;

    int n = in_sizes[0] / 7;
    int e = in_sizes[1] / 2;
    int g = out_size / OUTF - n;
    if (g < 0) g = 0;

    const int T = 256;
    int nb = (n + 1023) / 1024;                         // scan tiles (<= 64)

    k_hist<<<(e + T - 1) / T, T>>>(ei, batch, e, n);    // 0
    k_scan_lb<<<nb, 1024>>>(x, n, e);                   // 1
    k_fill<<<(e + T - 1) / T, T>>>(ei, e);              // 2
    k_l1<<<(n * 32 + T - 1) / T, T>>>(W1, b1, n);       // 3  <- profiled launch

    k_gemm_tc<128><<<(n + 127) / 128, 256>>>(W2, n);    // 4
    k_agg<128, true, false, true><<<(n * 32 + T - 1) / T, T>>>(b2, nullptr, batch, n); // 5

    k_gemm_tc<64><<<(n + 127) / 128, 256>>>(W3, n);     // 6
    if (g > 0) {
        k_agg<64, false, true, false><<<(n * 16 + T - 1) / T, T>>>(b3, out, batch, n); // 7
        k_pooldiv<<<(g * OUTF + T - 1) / T, T>>>(out + (size_t)n * OUTF, g);           // 8
    } else {
        k_agg<64, false, false, false><<<(n * 16 + T - 1) / T, T>>>(b3, out, batch, n);
    }
}